// round 2
// baseline (speedup 1.0000x reference)
#include <cuda_runtime.h>

// ---------------------------------------------------------------------------
// VectorQuantizer on GB300 — round 2: 8x16 register tile, swizzled smem.
// Inputs:  latents [16,64,64,64] NCHW fp32, emb_weight [1024,64] fp32
// Output (flattened concat, fp32): quantize | vq_loss | perplexity |
//                                  encodings | inds | distances
// ---------------------------------------------------------------------------

#define NPTS   65536
#define KCODES 1024
#define DDIM   64

static const long long Q_OFF     = 0LL;
static const long long LOSS_OFF  = 4194304LL;
static const long long PERP_OFF  = 4194305LL;
static const long long ENC_OFF   = 4194306LL;
static const long long INDS_OFF  = 71303170LL;
static const long long DIST_OFF  = 71368706LL;
static const long long TOTAL_OUT = 138477570LL;

__device__ int    g_counts[KCODES];
__device__ float  g_esq[KCODES];
__device__ double g_mse;

#define FMA2(d, a, b, c) \
    asm("fma.rn.f32x2 %0, %1, %2, %3;" : "=l"(d) : "l"(a), "l"(b), "l"(c))
#define PACKDUP(d, f) \
    asm("mov.b64 %0, {%1, %1};" : "=l"(d) : "r"(__float_as_uint(f)))

__device__ __forceinline__ float2 unpack2(unsigned long long v) {
    unsigned int lo, hi;
    asm("mov.b64 {%0, %1}, %2;" : "=r"(lo), "=r"(hi) : "l"(v));
    return make_float2(__uint_as_float(lo), __uint_as_float(hi));
}

// ---------------------------------------------------------------------------
// Kernel 0: reset accumulators, precompute ||e_k||^2 (vectorized)
// ---------------------------------------------------------------------------
__global__ void vq_prep(const float* __restrict__ emb) {
    int k = blockIdx.x * blockDim.x + threadIdx.x;   // 8 x 128 = 1024
    if (k == 0) g_mse = 0.0;
    if (k < KCODES) {
        g_counts[k] = 0;
        const float4* row = (const float4*)(emb + k * DDIM);
        float s = 0.f;
        #pragma unroll
        for (int i = 0; i < 16; ++i) {
            float4 v = row[i];
            s += v.x * v.x + v.y * v.y + v.z * v.z + v.w * v.w;
        }
        g_esq[k] = s;
    }
}

// ---------------------------------------------------------------------------
// Kernel 1: main. Block = 64 rows x 1024 codes, 256 threads, grid 1024.
// Thread micro-tile: 8 rows x 16 codes (64 f32x2 accumulators).
// smem layout (dynamic, 87040 B):
//   sx   [64][64]        x transposed (d-major)
//   se   [64][256]       emb chunk, d-major, 16B-block XOR-swizzled by d>>2
//   sesq [1024]          ||e||^2
//   xsq  [64]            ||x||^2 per row
//   spack[64] (u64)      packed (dist_bits<<32 | code) running min
//   sind [64]            final argmin index
// ---------------------------------------------------------------------------
template <bool FULL>
__global__ void __launch_bounds__(256, 1)
vq_main(const float* __restrict__ lat, const float* __restrict__ emb,
        float* __restrict__ out) {
    extern __shared__ float sm[];
    float* sx   = sm;                 // 4096 floats
    float* se   = sm + 4096;          // 16384 floats
    float* sesq = sm + 20480;         // 1024
    float* xsq  = sm + 21504;         // 64
    unsigned long long* spack = (unsigned long long*)(sm + 21568);  // 64 u64
    int*   sind = (int*)(sm + 21696); // 64 ints

    const int tid = threadIdx.x;
    const int n0  = blockIdx.x * 64;
    const int b   = n0 >> 12;
    const int hw0 = n0 & 4095;
    const int tr  = tid >> 4;          // 0..15, rows tr*8..tr*8+7... (tr<8? no)
    const int tc  = tid & 15;          // 0..15, codes tc*16..+15 per chunk
    // NOTE: tr in 0..15 but only 8 row-groups exist -> rows = (tr & 7)*8?  No:
    // 256 threads = 8 row-groups x 16 code-groups x 2?  Correct mapping below.
    // We use tr8 = tid >> 5 gives 8 groups of 8 rows? rows/block=64 = 8grp*8.
    const int rgrp = tid >> 5;         // 0..7 -> rows rgrp*8..+7
    const int cgrp = tid & 31;         // 0..31 -> codes cgrp*8?  -- see below

    // Re-derive clean mapping: 256 threads = 8 row-groups(8 rows) x 16
    // code-groups(16 codes) covers 64 rows x 256 codes per chunk. Use:
    const int trr = tid >> 4;   // 16 values — too many row groups. Instead:
    (void)tr; (void)trr; (void)rgrp; (void)cgrp; (void)tc;
    const int ty = tid / 16;    // 0..15
    const int tx = tid % 16;    // 0..15
    // 16x16 thread grid: ty -> 8-row group would need 128 rows. We have 64
    // rows, so pair up: row group = ty & 7 (8 groups), code half = ty >> 3.
    const int rg = ty & 7;              // rows rg*8 .. rg*8+7
    const int ch = ty >> 3;             // 0/1: which 128-code half of chunk
    const int cg = ch * 8 + (tx >> 1);  // not used — simpler: codes below
    (void)cg;
    // Final mapping: thread covers rows rg*8..+7 and codes (ch*128 +
    // tx*8 .. +7)?? That is 8 codes (4 pairs) -> tile 8x8, NOT 8x16.
    // To keep 8x16 with 64 rows we need 8x16=128 threads per 256-code strip;
    // 256 threads cover 64 rows x 512 codes -> chunk = 512 codes, 2 chunks.
    const int C_HALF = ch;              // which 256-code half of 512 chunk
    const int cbase16 = tx * 16;        // 16 codes within the 256 half

    // load x tile (coalesced over r)
    #pragma unroll
    for (int i = 0; i < 16; ++i) {
        int idx = tid + i * 256;
        int d = idx >> 6, r = idx & 63;
        sx[d * 64 + r] = lat[b * 262144 + d * 4096 + hw0 + r];
    }
    // esq -> smem
    #pragma unroll
    for (int i = 0; i < 4; ++i)
        sesq[tid + i * 256] = g_esq[tid + i * 256];
    if (tid < 64) spack[tid] = 0xFFFFFFFFFFFFFFFFULL;
    __syncthreads();
    if (tid < 64) {
        float s = 0.f;
        #pragma unroll
        for (int d = 0; d < 64; ++d) { float v = sx[d * 64 + tid]; s += v * v; }
        xsq[tid] = s;
    }

    unsigned long long best[8];
    #pragma unroll
    for (int i = 0; i < 8; ++i) best[i] = 0xFFFFFFFFFFFFFFFFULL;

    // 2 chunks of 512 codes; each 256-thread block: warp owns rows via rg,
    // codes via (C_HALF*256 + tx*16) within the 512-code chunk.
    for (int chunk = 0; chunk < 2; ++chunk) {
        const int kbase = chunk * 512 + C_HALF * 256;   // this thread's strip
        __syncthreads();
        // load se: both 256-code halves stored: se covers 512 codes? smem
        // budget: 64 x 512 floats = 128KB too big. Instead each half of the
        // block loads ITS OWN 256-code strip into its half of se:
        // se physical: [d][256] per half -> two halves share the same se
        // array? They need distinct storage: se2 size 64x512 = 128KB. Too
        // much. Solution: se holds 256 codes; halves alternate chunks:
        // chunk index for this thread = chunk*2 + C_HALF, 2 outer iters
        // cover 4 strips of 256 -> but both halves must load the SAME se.
        // => fall back: all 256 threads cooperate on ONE 256-code strip,
        // thread tile 8 rows x 16 codes needs 128 threads -> use 2-row-
        // group replication: rg in 0..7 from ty&7, second half (ch=1)
        // handles rows rg*8+?? -- rows only 64.
        (void)kbase;
        break; // placeholder — real loop below
    }

    // ----- actual clean implementation: 128-row blocks -----
    // (see vq_main2)
    (void)best;
}

// ---------------------------------------------------------------------------
// Clean main kernel: Block = 128 rows x 1024 codes, 256 threads, grid 512.
// Thread grid 16x16: ty -> rows ty*8..+7 (128 rows), tx -> codes tx*16..+15
// within a 256-code chunk (4 chunks).
// smem: sx[64][128] 32KB, se[64][256] 64KB (swizzled), sesq 4KB, xsq 512B,
//       spack 1KB, sind 512B  => ~102.5KB, occupancy 1 block/SM.
// ---------------------------------------------------------------------------
template <bool FULL>
__global__ void __launch_bounds__(256, 1)
vq_main2(const float* __restrict__ lat, const float* __restrict__ emb,
         float* __restrict__ out) {
    extern __shared__ float sm[];
    float* sx   = sm;                  // 64*128 = 8192 floats
    float* se   = sm + 8192;           // 64*256 = 16384 floats
    float* sesq = sm + 24576;          // 1024
    float* xsq  = sm + 25600;          // 128
    unsigned long long* spack = (unsigned long long*)(sm + 25728); // 128 u64
    int*   sind = (int*)(sm + 25984);  // 128 ints

    const int tid = threadIdx.x;
    const int n0  = blockIdx.x * 128;
    const int b   = n0 >> 12;
    const int hw0 = n0 & 4095;
    const int ty  = tid >> 4;          // row group: rows ty*8..+7
    const int tx  = tid & 15;          // code group: 16 codes

    // x tile: sx[d][r], r = 0..127 (coalesced over r)
    #pragma unroll
    for (int i = 0; i < 32; ++i) {
        int idx = tid + i * 256;
        int d = idx >> 7, r = idx & 127;
        sx[d * 128 + r] = lat[b * 262144 + d * 4096 + hw0 + r];
    }
    #pragma unroll
    for (int i = 0; i < 4; ++i)
        sesq[tid + i * 256] = g_esq[tid + i * 256];
    if (tid < 128) spack[tid] = 0xFFFFFFFFFFFFFFFFULL;
    __syncthreads();
    if (tid < 128) {
        float s = 0.f;
        #pragma unroll
        for (int d = 0; d < 64; ++d) { float v = sx[d * 128 + tid]; s += v * v; }
        xsq[tid] = s;
    }

    unsigned long long best[8];
    #pragma unroll
    for (int i = 0; i < 8; ++i) best[i] = 0xFFFFFFFFFFFFFFFFULL;

    const int tx4 = tx << 2;

    for (int chunk = 0; chunk < 4; ++chunk) {
        __syncthreads();
        // gmem -> smem transpose with 16B-block XOR swizzle (col_blk ^= dq)
        const float4* src = (const float4*)emb + chunk * 4096;
        #pragma unroll
        for (int i = 0; i < 16; ++i) {
            int fidx = tid + i * 256;
            int k  = fidx >> 4;        // code 0..255
            int dq = fidx & 15;        // d-quad
            float4 v = src[fidx];
            int col = ((((k >> 2) ^ dq) << 2) | (k & 3));
            float* p = se + (dq * 4) * 256 + col;
            p[0]   = v.x;
            p[256] = v.y;
            p[512] = v.z;
            p[768] = v.w;
        }
        __syncthreads();

        unsigned long long acc[8][8];
        #pragma unroll
        for (int i = 0; i < 8; ++i)
            #pragma unroll
            for (int j = 0; j < 8; ++j) acc[i][j] = 0ULL;

        #pragma unroll 2
        for (int dq = 0; dq < 16; ++dq) {
            const int c0 = ((tx4 + 0) ^ dq) << 2;
            const int c1 = ((tx4 + 1) ^ dq) << 2;
            const int c2 = ((tx4 + 2) ^ dq) << 2;
            const int c3 = ((tx4 + 3) ^ dq) << 2;
            #pragma unroll
            for (int s = 0; s < 4; ++s) {
                const int d = dq * 4 + s;
                const float* xr = sx + d * 128 + ty * 8;
                const float* er = se + d * 256;
                float4 xa = *(const float4*)(xr);
                float4 xb = *(const float4*)(xr + 4);
                ulonglong2 e0 = *(const ulonglong2*)(er + c0);
                ulonglong2 e1 = *(const ulonglong2*)(er + c1);
                ulonglong2 e2 = *(const ulonglong2*)(er + c2);
                ulonglong2 e3 = *(const ulonglong2*)(er + c3);
                float xf[8] = {xa.x, xa.y, xa.z, xa.w, xb.x, xb.y, xb.z, xb.w};
                #pragma unroll
                for (int r = 0; r < 8; ++r) {
                    unsigned long long xp;
                    PACKDUP(xp, xf[r]);
                    FMA2(acc[r][0], xp, e0.x, acc[r][0]);
                    FMA2(acc[r][1], xp, e0.y, acc[r][1]);
                    FMA2(acc[r][2], xp, e1.x, acc[r][2]);
                    FMA2(acc[r][3], xp, e1.y, acc[r][3]);
                    FMA2(acc[r][4], xp, e2.x, acc[r][4]);
                    FMA2(acc[r][5], xp, e2.y, acc[r][5]);
                    FMA2(acc[r][6], xp, e3.x, acc[r][6]);
                    FMA2(acc[r][7], xp, e3.y, acc[r][7]);
                }
            }
        }

        // epilogue: distances, running packed argmin, streaming stores
        const int cb = chunk * 256 + (tx << 4);
        const float4* sq4 = (const float4*)(sesq + cb);
        float4 q0 = sq4[0], q1 = sq4[1], q2 = sq4[2], q3 = sq4[3];
        float eqs[16] = {q0.x, q0.y, q0.z, q0.w, q1.x, q1.y, q1.z, q1.w,
                         q2.x, q2.y, q2.z, q2.w, q3.x, q3.y, q3.z, q3.w};
        #pragma unroll
        for (int i = 0; i < 8; ++i) {
            const float xs = xsq[ty * 8 + i];
            const long long nrow = n0 + ty * 8 + i;
            float* dp = out + DIST_OFF + nrow * 1024 + cb;
            float* ep = out + ENC_OFF  + nrow * 1024 + cb;
            #pragma unroll
            for (int j = 0; j < 8; ++j) {
                float2 p = unpack2(acc[i][j]);
                float d0 = fmaf(-2.f, p.x, xs + eqs[2 * j]);
                float d1 = fmaf(-2.f, p.y, xs + eqs[2 * j + 1]);
                unsigned long long pk0 =
                    ((unsigned long long)__float_as_uint(d0) << 32) |
                    (unsigned)(cb + 2 * j);
                unsigned long long pk1 =
                    ((unsigned long long)__float_as_uint(d1) << 32) |
                    (unsigned)(cb + 2 * j + 1);
                if (pk0 < best[i]) best[i] = pk0;
                if (pk1 < best[i]) best[i] = pk1;
                if (FULL) {
                    __stcs((float2*)(dp + 2 * j), make_float2(d0, d1));
                    __stcs((float2*)(ep + 2 * j), make_float2(0.f, 0.f));
                }
            }
        }
    }

    #pragma unroll
    for (int i = 0; i < 8; ++i)
        atomicMin(&spack[ty * 8 + i], best[i]);
    __syncthreads();

    if (tid < 128) {
        unsigned long long pk = spack[tid];
        int   bi = (int)(unsigned)(pk & 0xFFFFFFFFULL);
        float bv = __uint_as_float((unsigned)(pk >> 32));
        sind[tid] = bi;
        atomicAdd(&g_counts[bi], 1);
        if (FULL) {
            int n = n0 + tid;
            out[INDS_OFF + n] = (float)bi;
            out[ENC_OFF + (long long)n * 1024 + bi] = 1.0f;
        }
        float s = bv;
        #pragma unroll
        for (int off = 16; off > 0; off >>= 1)
            s += __shfl_down_sync(0xffffffffu, s, off);
        if ((tid & 31) == 0) atomicAdd(&g_mse, (double)s);
    }
    __syncthreads();

    // quantize gather: coalesced over r
    #pragma unroll
    for (int i = 0; i < 32; ++i) {
        int idx = tid + i * 256;
        int r = idx & 127, d = idx >> 7;
        __stcs(out + b * 262144 + d * 4096 + hw0 + r,
               __ldg(emb + sind[r] * 64 + d));
    }
}

// ---------------------------------------------------------------------------
// Kernel 2: loss + perplexity
// ---------------------------------------------------------------------------
__global__ void vq_finalize(float* __restrict__ out) {
    __shared__ float red[32];
    int t = threadIdx.x;                    // 1024 threads
    float p = (float)g_counts[t] * (1.0f / 65536.0f);
    float v = p * logf(p + 1e-10f);
    #pragma unroll
    for (int off = 16; off > 0; off >>= 1)
        v += __shfl_down_sync(0xffffffffu, v, off);
    if ((t & 31) == 0) red[t >> 5] = v;
    __syncthreads();
    if (t < 32) {
        float s = red[t];
        #pragma unroll
        for (int off = 16; off > 0; off >>= 1)
            s += __shfl_down_sync(0xffffffffu, s, off);
        if (t == 0) {
            out[PERP_OFF] = expf(-s);
            out[LOSS_OFF] = (float)(g_mse * (1.25 / (65536.0 * 64.0)));
        }
    }
}

// ---------------------------------------------------------------------------
extern "C" void kernel_launch(void* const* d_in, const int* in_sizes, int n_in,
                              void* d_out, int out_size) {
    const float* lat = (const float*)d_in[0];
    const float* emb = (const float*)d_in[1];
    if (n_in >= 2 && in_sizes[0] == KCODES * DDIM && in_sizes[1] == NPTS * DDIM) {
        lat = (const float*)d_in[1];
        emb = (const float*)d_in[0];
    }
    float* out = (float*)d_out;
    const bool full = ((long long)out_size >= TOTAL_OUT);

    // smem: 26112 floats + spack/sind tail = 26112*4 = 104448 B covers all
    const int smem_bytes = 26112 * 4;   // 104448
    static int configured = -1;
    if (configured < 0) {
        cudaFuncSetAttribute(vq_main2<true>,
                             cudaFuncAttributeMaxDynamicSharedMemorySize,
                             smem_bytes);
        cudaFuncSetAttribute(vq_main2<false>,
                             cudaFuncAttributeMaxDynamicSharedMemorySize,
                             smem_bytes);
        configured = 1;
    }

    vq_prep<<<8, 128>>>(emb);
    if (full) {
        vq_main2<true><<<512, 256, smem_bytes>>>(lat, emb, out);
        vq_finalize<<<1, 1024>>>(out);
    } else {
        vq_main2<false><<<512, 256, smem_bytes>>>(lat, emb, out);
    }
}

// round 3
// speedup vs baseline: 1.2559x; 1.2559x over previous
#include <cuda_runtime.h>

// ---------------------------------------------------------------------------
// VectorQuantizer on GB300 — round 3: single fused kernel.
// latents [16,64,64,64] NCHW fp32, emb_weight [1024,64] fp32.
// out: quantize | vq_loss | perplexity | encodings | inds | distances
// ---------------------------------------------------------------------------

#define ROWPAD 132   // 128 floats + 4 pad (16B-aligned rows, bank-spread)

static const long long Q_OFF     = 0LL;
static const long long LOSS_OFF  = 4194304LL;
static const long long PERP_OFF  = 4194305LL;
static const long long ENC_OFF   = 4194306LL;
static const long long INDS_OFF  = 71303170LL;
static const long long DIST_OFF  = 71368706LL;
static const long long TOTAL_OUT = 138477570LL;

__device__ int          g_inds[65536];
__device__ float        g_msep[1024];
__device__ unsigned int g_ticket;   // monotonic; (old & 1023)==1023 -> last block

#define FMA2(d, a, b, c) \
    asm("fma.rn.f32x2 %0, %1, %2, %3;" : "=l"(d) : "l"(a), "l"(b), "l"(c))

__device__ __forceinline__ float2 unpack2(unsigned long long v) {
    unsigned int lo, hi;
    asm("mov.b64 {%0, %1}, %2;" : "=r"(lo), "=r"(hi) : "l"(v));
    return make_float2(__uint_as_float(lo), __uint_as_float(hi));
}

// smem float offsets
#define SXD_OFF   0        // 64 x 132 (x duplicated: row r at cols 2r,2r+1)
#define SE_OFF    8448     // 64 x 132 (128-code chunk, 16B-block XOR swizzle)
#define SCQ_OFF   16896    // 128  ||e||^2 of current chunk
#define XSQ_OFF   17024    // 64   ||x||^2 per row
#define SPACK_OFF 17088    // 64 u64 (128 floats)
#define SIND_OFF  17216    // 64 ints
#define SRED_OFF  17280    // 16 floats
#define SFLAG_OFF 17316    // 1 int
#define SMEM_FLOATS 17320

template <bool FULL>
__global__ void __launch_bounds__(256, 3)
vq_fused(const float* __restrict__ lat, const float* __restrict__ emb,
         float* __restrict__ out) {
    extern __shared__ float sm[];
    float* sxd = sm + SXD_OFF;
    float* se  = sm + SE_OFF;
    float* scq = sm + SCQ_OFF;
    float* xsq = sm + XSQ_OFF;
    unsigned long long* spack = (unsigned long long*)(sm + SPACK_OFF);
    int*   sind  = (int*)(sm + SIND_OFF);
    float* sred  = sm + SRED_OFF;
    int*   sflag = (int*)(sm + SFLAG_OFF);

    const int tid = threadIdx.x;
    const int n0  = blockIdx.x * 64;   // 64 rows per block
    const int b   = n0 >> 12;
    const int hw0 = n0 & 4095;
    const int ty  = tid >> 4;          // rows ty*4 .. +3
    const int tx  = tid & 15;          // codes tx*8 .. +7 per 128-code chunk

    // ---- load x tile, duplicated: sxd[d][2r]=sxd[d][2r+1]=x[r][d] ----
    {
        const float4* lat4 = (const float4*)lat;
        #pragma unroll
        for (int i = 0; i < 4; ++i) {
            int idx = tid + i * 256;         // 1024 float4 = 64 d x 16 quads
            int d = idx >> 4, q = idx & 15;
            float4 v = lat4[b * 65536 + d * 1024 + (hw0 >> 2) + q];
            float* p = sxd + d * ROWPAD + 8 * q;
            *(float4*)(p)     = make_float4(v.x, v.x, v.y, v.y);
            *(float4*)(p + 4) = make_float4(v.z, v.z, v.w, v.w);
        }
    }
    if (tid < 64) spack[tid] = 0xFFFFFFFFFFFFFFFFULL;
    __syncthreads();
    if (tid < 64) {
        float s = 0.f;
        #pragma unroll
        for (int d = 0; d < 64; ++d) {
            float v = sxd[d * ROWPAD + 2 * tid];
            s += v * v;
        }
        xsq[tid] = s;   // read in epilogue, after chunk-A sync
    }

    float bv[4] = {3.4e38f, 3.4e38f, 3.4e38f, 3.4e38f};
    int   bi[4] = {0, 0, 0, 0};

    for (int chunk = 0; chunk < 8; ++chunk) {
        __syncthreads();   // A: protects se/scq reuse + xsq/spack first time

        // gmem -> smem transpose, 16B-block XOR swizzle (block = cb ^ dq)
        const float4* src = (const float4*)emb + chunk * 2048;
        #pragma unroll
        for (int i = 0; i < 8; ++i) {
            int fidx = tid + i * 256;          // 128 codes x 16 d-quads
            int k = fidx >> 4, dq = fidx & 15;
            float4 v = src[fidx];
            float* p = se + dq * 4 * ROWPAD + (((k >> 2) ^ dq) << 2) + (k & 3);
            p[0]          = v.x;
            p[ROWPAD]     = v.y;
            p[2 * ROWPAD] = v.z;
            p[3 * ROWPAD] = v.w;
        }
        __syncthreads();   // B

        // ||e||^2 for this chunk's 128 codes (from swizzled smem)
        if (tid < 128) {
            int cbb = tid >> 2, cl = tid & 3;
            float s = 0.f;
            #pragma unroll
            for (int dq = 0; dq < 16; ++dq) {
                const float* p = se + dq * 4 * ROWPAD + ((cbb ^ dq) << 2) + cl;
                float a0 = p[0], a1 = p[ROWPAD], a2 = p[2 * ROWPAD], a3 = p[3 * ROWPAD];
                s += a0 * a0 + a1 * a1 + a2 * a2 + a3 * a3;
            }
            scq[tid] = s;
        }

        // ---- main accumulation: 4 rows x 8 codes, f32x2 packed ----
        unsigned long long acc[4][4];
        #pragma unroll
        for (int r = 0; r < 4; ++r)
            #pragma unroll
            for (int p = 0; p < 4; ++p) acc[r][p] = 0ULL;

        const float* xb = sxd + ty * 8;
        const int cb0 = tx * 2, cb1 = tx * 2 + 1;
        #pragma unroll 2
        for (int dq = 0; dq < 16; ++dq) {
            const float* xr  = xb + dq * (4 * ROWPAD);
            const float* er0 = se + dq * (4 * ROWPAD) + ((cb0 ^ dq) << 2);
            const float* er1 = se + dq * (4 * ROWPAD) + ((cb1 ^ dq) << 2);
            #pragma unroll
            for (int s4 = 0; s4 < 4; ++s4) {
                ulonglong2 xv0 = *(const ulonglong2*)(xr + s4 * ROWPAD);      // rows 0,1 (dup)
                ulonglong2 xv1 = *(const ulonglong2*)(xr + s4 * ROWPAD + 4);  // rows 2,3 (dup)
                ulonglong2 e0  = *(const ulonglong2*)(er0 + s4 * ROWPAD);     // codes 0-3
                ulonglong2 e1  = *(const ulonglong2*)(er1 + s4 * ROWPAD);     // codes 4-7
                FMA2(acc[0][0], xv0.x, e0.x, acc[0][0]);
                FMA2(acc[0][1], xv0.x, e0.y, acc[0][1]);
                FMA2(acc[0][2], xv0.x, e1.x, acc[0][2]);
                FMA2(acc[0][3], xv0.x, e1.y, acc[0][3]);
                FMA2(acc[1][0], xv0.y, e0.x, acc[1][0]);
                FMA2(acc[1][1], xv0.y, e0.y, acc[1][1]);
                FMA2(acc[1][2], xv0.y, e1.x, acc[1][2]);
                FMA2(acc[1][3], xv0.y, e1.y, acc[1][3]);
                FMA2(acc[2][0], xv1.x, e0.x, acc[2][0]);
                FMA2(acc[2][1], xv1.x, e0.y, acc[2][1]);
                FMA2(acc[2][2], xv1.x, e1.x, acc[2][2]);
                FMA2(acc[2][3], xv1.x, e1.y, acc[2][3]);
                FMA2(acc[3][0], xv1.y, e0.x, acc[3][0]);
                FMA2(acc[3][1], xv1.y, e0.y, acc[3][1]);
                FMA2(acc[3][2], xv1.y, e1.x, acc[3][2]);
                FMA2(acc[3][3], xv1.y, e1.y, acc[3][3]);
            }
        }
        __syncthreads();   // C: scq ready for everyone

        // ---- epilogue: distances, running argmin, streaming stores ----
        const int cbase = chunk * 128 + tx * 8;
        const float4 eqa = *(const float4*)(scq + tx * 8);
        const float4 eqb = *(const float4*)(scq + tx * 8 + 4);
        const float eq[8] = {eqa.x, eqa.y, eqa.z, eqa.w,
                             eqb.x, eqb.y, eqb.z, eqb.w};
        #pragma unroll
        for (int r = 0; r < 4; ++r) {
            const float xs = xsq[ty * 4 + r];
            float dd[8];
            #pragma unroll
            for (int p = 0; p < 4; ++p) {
                float2 pr = unpack2(acc[r][p]);
                dd[2 * p]     = fmaf(-2.f, pr.x, xs + eq[2 * p]);
                dd[2 * p + 1] = fmaf(-2.f, pr.y, xs + eq[2 * p + 1]);
            }
            #pragma unroll
            for (int j = 0; j < 8; ++j)
                if (dd[j] < bv[r]) { bv[r] = dd[j]; bi[r] = cbase + j; }
            if (FULL) {
                long long nrow = n0 + ty * 4 + r;
                float* dp = out + DIST_OFF + nrow * 1024 + cbase;
                float* ep = out + ENC_OFF  + nrow * 1024 + cbase;
                __stcs((float2*)dp,       make_float2(dd[0], dd[1]));
                __stcs((float2*)(dp + 2), make_float2(dd[2], dd[3]));
                __stcs((float2*)(dp + 4), make_float2(dd[4], dd[5]));
                __stcs((float2*)(dp + 6), make_float2(dd[6], dd[7]));
                const float2 z = make_float2(0.f, 0.f);
                __stcs((float2*)ep,       z);
                __stcs((float2*)(ep + 2), z);
                __stcs((float2*)(ep + 4), z);
                __stcs((float2*)(ep + 6), z);
            }
        }
    }

    // ---- per-row argmin across threads: packed (dist_bits, idx) atomicMin ----
    #pragma unroll
    for (int r = 0; r < 4; ++r) {
        unsigned long long pk =
            ((unsigned long long)__float_as_uint(bv[r]) << 32) | (unsigned)bi[r];
        atomicMin(&spack[ty * 4 + r], pk);
    }
    __syncthreads();

    if (tid < 64) {
        unsigned long long pk = spack[tid];
        int   ii = (int)(unsigned)(pk & 0xFFFFFFFFULL);
        float mv = __uint_as_float((unsigned)(pk >> 32));
        sind[tid] = ii;
        g_inds[n0 + tid] = ii;
        if (FULL) {
            out[INDS_OFF + n0 + tid] = (float)ii;
            out[ENC_OFF + (long long)(n0 + tid) * 1024 + ii] = 1.0f;
        }
        float s = mv;   // min dist == ||x - e||^2 (same expansion as ref outputs)
        #pragma unroll
        for (int o = 16; o > 0; o >>= 1)
            s += __shfl_down_sync(0xffffffffu, s, o);
        if ((tid & 31) == 0) sred[tid >> 5] = s;
    }
    __syncthreads();
    if (tid == 0) g_msep[blockIdx.x] = sred[0] + sred[1];

    // ---- quantize gather (coalesced stores over r) ----
    #pragma unroll
    for (int i = 0; i < 16; ++i) {
        int idx = tid + i * 256;
        int r = idx & 63, d = idx >> 6;
        out[Q_OFF + b * 262144 + d * 4096 + hw0 + r] =
            __ldg(emb + sind[r] * 64 + d);
    }

    // ---- last-block finalize (threadfence ticket) ----
    __syncthreads();
    if (tid == 0) {
        __threadfence();
        unsigned old = atomicAdd(&g_ticket, 1u);
        sflag[0] = ((old & 1023u) == 1023u) ? 1 : 0;
    }
    __syncthreads();
    if (sflag[0]) {
        __threadfence();
        int* hist = (int*)sxd;
        #pragma unroll
        for (int i = 0; i < 4; ++i) hist[tid + i * 256] = 0;
        __syncthreads();
        #pragma unroll 4
        for (int i = 0; i < 256; ++i)
            atomicAdd(&hist[g_inds[tid + i * 256]], 1);
        __syncthreads();
        float ent = 0.f, msel = 0.f;
        #pragma unroll
        for (int i = 0; i < 4; ++i) {
            float p = (float)hist[tid + i * 256] * (1.0f / 65536.0f);
            ent  += p * logf(p + 1e-10f);
            msel += g_msep[tid + i * 256];
        }
        #pragma unroll
        for (int o = 16; o > 0; o >>= 1) {
            ent  += __shfl_down_sync(0xffffffffu, ent,  o);
            msel += __shfl_down_sync(0xffffffffu, msel, o);
        }
        if ((tid & 31) == 0) { sred[tid >> 5] = ent; sred[8 + (tid >> 5)] = msel; }
        __syncthreads();
        if (tid == 0 && FULL) {
            float e = 0.f, m = 0.f;
            #pragma unroll
            for (int w = 0; w < 8; ++w) { e += sred[w]; m += sred[8 + w]; }
            out[PERP_OFF] = expf(-e);
            out[LOSS_OFF] = m * (1.25f / (65536.0f * 64.0f));
        }
    }
}

// ---------------------------------------------------------------------------
extern "C" void kernel_launch(void* const* d_in, const int* in_sizes, int n_in,
                              void* d_out, int out_size) {
    const float* lat = (const float*)d_in[0];
    const float* emb = (const float*)d_in[1];
    if (n_in >= 2 && in_sizes[0] == 1024 * 64 && in_sizes[1] == 65536 * 64) {
        lat = (const float*)d_in[1];
        emb = (const float*)d_in[0];
    }
    float* out = (float*)d_out;
    const bool full = ((long long)out_size >= TOTAL_OUT);
    const int smem_bytes = SMEM_FLOATS * 4;   // 69280

    static int cfg = 0;
    if (!cfg) {
        cudaFuncSetAttribute(vq_fused<true>,
                             cudaFuncAttributeMaxDynamicSharedMemorySize, smem_bytes);
        cudaFuncSetAttribute(vq_fused<false>,
                             cudaFuncAttributeMaxDynamicSharedMemorySize, smem_bytes);
        cfg = 1;
    }
    if (full) vq_fused<true><<<1024, 256, smem_bytes>>>(lat, emb, out);
    else      vq_fused<false><<<1024, 256, smem_bytes>>>(lat, emb, out);
}

// round 4
// speedup vs baseline: 1.7080x; 1.3599x over previous
#include <cuda_runtime.h>

// ---------------------------------------------------------------------------
// VectorQuantizer on GB300 — round 4: 8x8 tile, row-paired f32x2 accumulators,
// no smem data duplication (1 byte of LDS return per FMA).
// ---------------------------------------------------------------------------

#define SXROW 68     // 64 rows + pad
#define SEROW 132    // 128 codes + pad

static const long long Q_OFF     = 0LL;
static const long long LOSS_OFF  = 4194304LL;
static const long long PERP_OFF  = 4194305LL;
static const long long ENC_OFF   = 4194306LL;
static const long long INDS_OFF  = 71303170LL;
static const long long DIST_OFF  = 71368706LL;
static const long long TOTAL_OUT = 138477570LL;

__device__ int          g_inds[65536];
__device__ float        g_msep[1024];
__device__ unsigned int g_ticket;   // monotonic across replays

#define FMA2(d, a, b, c) \
    asm("fma.rn.f32x2 %0, %1, %2, %3;" : "=l"(d) : "l"(a), "l"(b), "l"(c))
#define DUPF(d, f) \
    asm("mov.b64 %0, {%1, %1};" : "=l"(d) : "r"(__float_as_uint(f)))

__device__ __forceinline__ float2 unpack2(unsigned long long v) {
    unsigned int lo, hi;
    asm("mov.b64 {%0, %1}, %2;" : "=r"(lo), "=r"(hi) : "l"(v));
    return make_float2(__uint_as_float(lo), __uint_as_float(hi));
}

// smem float offsets
#define SX_OFF   0        // 64*68  = 4352
#define SE_OFF   4352     // 64*132 = 8448
#define SCQ_OFF  12800    // 128
#define XSQ_OFF  12928    // 64
#define SPK_OFF  12992    // 64 u64 (128 floats)
#define SIND_OFF 13120    // 64
#define SRED_OFF 13184    // 16
#define SFLG_OFF 13200    // 1
#define SMEMF    13204

template <bool FULL>
__global__ void __launch_bounds__(128, 4)
vq_fused(const float* __restrict__ lat, const float* __restrict__ emb,
         float* __restrict__ out) {
    extern __shared__ float sm[];
    float* sx  = sm + SX_OFF;
    float* se  = sm + SE_OFF;
    float* scq = sm + SCQ_OFF;
    float* xsq = sm + XSQ_OFF;
    unsigned long long* spk = (unsigned long long*)(sm + SPK_OFF);
    int*   sind = (int*)(sm + SIND_OFF);
    float* sred = sm + SRED_OFF;
    int*   sflg = (int*)(sm + SFLG_OFF);

    const int tid = threadIdx.x;
    const int n0  = blockIdx.x * 64;    // 64 rows per block
    const int b   = n0 >> 12;
    const int hw0 = n0 & 4095;
    const int ty  = tid >> 4;            // 0..7: rows ty*8..+7
    const int tx  = tid & 15;            // 8 codes per 128-code chunk

    // ---- x tile: sx[d][r] ----
    {
        const float4* lat4 = (const float4*)lat;
        #pragma unroll
        for (int i = 0; i < 8; ++i) {
            int idx = tid + i * 128;          // 1024 float4
            int d = idx >> 4, q = idx & 15;
            float4 v = lat4[b * 65536 + d * 1024 + (hw0 >> 2) + q];
            *(float4*)(sx + d * SXROW + q * 4) = v;
        }
    }
    if (tid < 64) spk[tid] = 0xFFFFFFFFFFFFFFFFULL;
    __syncthreads();
    if (tid < 64) {
        float s = 0.f;
        #pragma unroll
        for (int d = 0; d < 64; ++d) { float v = sx[d * SXROW + tid]; s += v * v; }
        xsq[tid] = s;
    }

    float bv[8]; int bi[8];
    #pragma unroll
    for (int r = 0; r < 8; ++r) { bv[r] = 3.4e38f; bi[r] = 0; }

    for (int chunk = 0; chunk < 8; ++chunk) {
        __syncthreads();   // A: se/scq reuse safe, xsq/spk ready first iter
        // gmem -> smem transpose, 16B-block XOR swizzle by dq
        const float4* src = (const float4*)emb + chunk * 2048;
        #pragma unroll
        for (int i = 0; i < 16; ++i) {
            int fidx = tid + i * 128;          // 128 codes x 16 d-quads
            int k = fidx >> 4, dq = fidx & 15;
            float4 v = src[fidx];
            float* p = se + dq * 4 * SEROW + (((k >> 2) ^ dq) << 2) + (k & 3);
            p[0]         = v.x;
            p[SEROW]     = v.y;
            p[2 * SEROW] = v.z;
            p[3 * SEROW] = v.w;
        }
        __syncthreads();   // B

        // ||e||^2 for the chunk's 128 codes (one code per thread)
        {
            int cb = tid >> 2, cl = tid & 3;
            float s = 0.f;
            #pragma unroll
            for (int dq = 0; dq < 16; ++dq) {
                const float* p = se + dq * 4 * SEROW + ((cb ^ dq) << 2) + cl;
                float a0 = p[0], a1 = p[SEROW], a2 = p[2 * SEROW], a3 = p[3 * SEROW];
                s += a0 * a0 + a1 * a1 + a2 * a2 + a3 * a3;
            }
            scq[tid] = s;
        }

        // ---- main: 8 rows (4 f32x2 pairs) x 8 codes ----
        unsigned long long acc[4][8];
        #pragma unroll
        for (int p = 0; p < 4; ++p)
            #pragma unroll
            for (int c = 0; c < 8; ++c) acc[p][c] = 0ULL;

        #pragma unroll 1
        for (int dq = 0; dq < 16; ++dq) {
            const int b0 = (((tx << 1)    ) ^ dq) << 2;
            const int b1 = (((tx << 1) + 1) ^ dq) << 2;
            #pragma unroll
            for (int j = 0; j < 4; ++j) {
                const int d = (dq << 2) + j;
                const float* xr = sx + d * SXROW + (ty << 3);
                const float* er = se + d * SEROW;
                ulonglong2 xa = *(const ulonglong2*)xr;        // rows 0-3 (2 pairs)
                ulonglong2 xb = *(const ulonglong2*)(xr + 4);  // rows 4-7
                float4 ea = *(const float4*)(er + b0);         // codes 0-3
                float4 eb = *(const float4*)(er + b1);         // codes 4-7
                unsigned long long ed0, ed1;
                DUPF(ed0, ea.x);
                FMA2(acc[0][0], xa.x, ed0, acc[0][0]);
                FMA2(acc[1][0], xa.y, ed0, acc[1][0]);
                FMA2(acc[2][0], xb.x, ed0, acc[2][0]);
                FMA2(acc[3][0], xb.y, ed0, acc[3][0]);
                DUPF(ed1, ea.y);
                FMA2(acc[0][1], xa.x, ed1, acc[0][1]);
                FMA2(acc[1][1], xa.y, ed1, acc[1][1]);
                FMA2(acc[2][1], xb.x, ed1, acc[2][1]);
                FMA2(acc[3][1], xb.y, ed1, acc[3][1]);
                DUPF(ed0, ea.z);
                FMA2(acc[0][2], xa.x, ed0, acc[0][2]);
                FMA2(acc[1][2], xa.y, ed0, acc[1][2]);
                FMA2(acc[2][2], xb.x, ed0, acc[2][2]);
                FMA2(acc[3][2], xb.y, ed0, acc[3][2]);
                DUPF(ed1, ea.w);
                FMA2(acc[0][3], xa.x, ed1, acc[0][3]);
                FMA2(acc[1][3], xa.y, ed1, acc[1][3]);
                FMA2(acc[2][3], xb.x, ed1, acc[2][3]);
                FMA2(acc[3][3], xb.y, ed1, acc[3][3]);
                DUPF(ed0, eb.x);
                FMA2(acc[0][4], xa.x, ed0, acc[0][4]);
                FMA2(acc[1][4], xa.y, ed0, acc[1][4]);
                FMA2(acc[2][4], xb.x, ed0, acc[2][4]);
                FMA2(acc[3][4], xb.y, ed0, acc[3][4]);
                DUPF(ed1, eb.y);
                FMA2(acc[0][5], xa.x, ed1, acc[0][5]);
                FMA2(acc[1][5], xa.y, ed1, acc[1][5]);
                FMA2(acc[2][5], xb.x, ed1, acc[2][5]);
                FMA2(acc[3][5], xb.y, ed1, acc[3][5]);
                DUPF(ed0, eb.z);
                FMA2(acc[0][6], xa.x, ed0, acc[0][6]);
                FMA2(acc[1][6], xa.y, ed0, acc[1][6]);
                FMA2(acc[2][6], xb.x, ed0, acc[2][6]);
                FMA2(acc[3][6], xb.y, ed0, acc[3][6]);
                DUPF(ed1, eb.w);
                FMA2(acc[0][7], xa.x, ed1, acc[0][7]);
                FMA2(acc[1][7], xa.y, ed1, acc[1][7]);
                FMA2(acc[2][7], xb.x, ed1, acc[2][7]);
                FMA2(acc[3][7], xb.y, ed1, acc[3][7]);
            }
        }
        __syncthreads();   // C: scq visible to all

        // ---- epilogue ----
        const int cbase = (chunk << 7) + (tx << 3);
        float4 qa = *(const float4*)(scq + (tx << 3));
        float4 qb = *(const float4*)(scq + (tx << 3) + 4);
        float eq[8] = {qa.x, qa.y, qa.z, qa.w, qb.x, qb.y, qb.z, qb.w};
        #pragma unroll
        for (int p = 0; p < 4; ++p) {
            const int r0 = (ty << 3) + (p << 1);
            const float xs0 = xsq[r0], xs1 = xsq[r0 + 1];
            float dd0[8], dd1[8];
            #pragma unroll
            for (int c = 0; c < 8; ++c) {
                float2 pr = unpack2(acc[p][c]);
                dd0[c] = fmaf(-2.f, pr.x, xs0 + eq[c]);
                dd1[c] = fmaf(-2.f, pr.y, xs1 + eq[c]);
                if (dd0[c] < bv[2 * p])     { bv[2 * p]     = dd0[c]; bi[2 * p]     = cbase + c; }
                if (dd1[c] < bv[2 * p + 1]) { bv[2 * p + 1] = dd1[c]; bi[2 * p + 1] = cbase + c; }
            }
            if (FULL) {
                long long nr = n0 + r0;
                float* dp = out + DIST_OFF + nr * 1024 + cbase;
                float* ep = out + ENC_OFF  + nr * 1024 + cbase;
                __stcs((float2*)(dp),        make_float2(dd0[0], dd0[1]));
                __stcs((float2*)(dp + 2),    make_float2(dd0[2], dd0[3]));
                __stcs((float2*)(dp + 4),    make_float2(dd0[4], dd0[5]));
                __stcs((float2*)(dp + 6),    make_float2(dd0[6], dd0[7]));
                __stcs((float2*)(dp + 1024), make_float2(dd1[0], dd1[1]));
                __stcs((float2*)(dp + 1026), make_float2(dd1[2], dd1[3]));
                __stcs((float2*)(dp + 1028), make_float2(dd1[4], dd1[5]));
                __stcs((float2*)(dp + 1030), make_float2(dd1[6], dd1[7]));
                const float2 z = make_float2(0.f, 0.f);
                __stcs((float2*)(ep),        z);
                __stcs((float2*)(ep + 2),    z);
                __stcs((float2*)(ep + 4),    z);
                __stcs((float2*)(ep + 6),    z);
                __stcs((float2*)(ep + 1024), z);
                __stcs((float2*)(ep + 1026), z);
                __stcs((float2*)(ep + 1028), z);
                __stcs((float2*)(ep + 1030), z);
            }
        }
    }

    // ---- per-row argmin across tx threads ----
    #pragma unroll
    for (int r = 0; r < 8; ++r) {
        unsigned long long pk =
            ((unsigned long long)__float_as_uint(bv[r]) << 32) | (unsigned)bi[r];
        atomicMin(&spk[(ty << 3) + r], pk);
    }
    __syncthreads();

    if (tid < 64) {
        unsigned long long pk = spk[tid];
        int   ii = (int)(unsigned)(pk & 0xFFFFFFFFULL);
        float mv = __uint_as_float((unsigned)(pk >> 32));
        sind[tid] = ii;
        g_inds[n0 + tid] = ii;
        if (FULL) {
            out[INDS_OFF + n0 + tid] = (float)ii;
            out[ENC_OFF + (long long)(n0 + tid) * 1024 + ii] = 1.0f;
        }
        float s = mv;
        #pragma unroll
        for (int o = 16; o > 0; o >>= 1)
            s += __shfl_down_sync(0xffffffffu, s, o);
        if ((tid & 31) == 0) sred[tid >> 5] = s;
    }
    __syncthreads();
    if (tid == 0) g_msep[blockIdx.x] = sred[0] + sred[1];

    // ---- quantize gather (coalesced over r) ----
    #pragma unroll
    for (int i = 0; i < 32; ++i) {
        int idx = tid + i * 128;
        int r = idx & 63, d = idx >> 6;
        out[Q_OFF + (long long)b * 262144 + d * 4096 + hw0 + r] =
            __ldg(emb + sind[r] * 64 + d);
    }

    // ---- last-block finalize ----
    __syncthreads();
    if (tid == 0) {
        __threadfence();
        unsigned old = atomicAdd(&g_ticket, 1u);
        sflg[0] = ((old & 1023u) == 1023u) ? 1 : 0;
    }
    __syncthreads();
    if (sflg[0]) {
        __threadfence();
        int* hist = (int*)sm;   // reuse sx region
        #pragma unroll
        for (int i = 0; i < 8; ++i) hist[tid + i * 128] = 0;
        __syncthreads();
        #pragma unroll 4
        for (int i = 0; i < 512; ++i)
            atomicAdd(&hist[g_inds[i * 128 + tid]], 1);
        __syncthreads();
        float ent = 0.f, msel = 0.f;
        #pragma unroll
        for (int i = 0; i < 8; ++i) {
            float p = (float)hist[tid + i * 128] * (1.0f / 65536.0f);
            ent  += p * logf(p + 1e-10f);
            msel += g_msep[tid + i * 128];
        }
        #pragma unroll
        for (int o = 16; o > 0; o >>= 1) {
            ent  += __shfl_down_sync(0xffffffffu, ent,  o);
            msel += __shfl_down_sync(0xffffffffu, msel, o);
        }
        if ((tid & 31) == 0) { sred[tid >> 5] = ent; sred[4 + (tid >> 5)] = msel; }
        __syncthreads();
        if (tid == 0 && FULL) {
            float e = sred[0] + sred[1] + sred[2] + sred[3];
            float m = sred[4] + sred[5] + sred[6] + sred[7];
            out[PERP_OFF] = expf(-e);
            out[LOSS_OFF] = m * (1.25f / (65536.0f * 64.0f));
        }
    }
}

// ---------------------------------------------------------------------------
extern "C" void kernel_launch(void* const* d_in, const int* in_sizes, int n_in,
                              void* d_out, int out_size) {
    const float* lat = (const float*)d_in[0];
    const float* emb = (const float*)d_in[1];
    if (n_in >= 2 && in_sizes[0] == 1024 * 64 && in_sizes[1] == 65536 * 64) {
        lat = (const float*)d_in[1];
        emb = (const float*)d_in[0];
    }
    float* out = (float*)d_out;
    const bool full = ((long long)out_size >= TOTAL_OUT);
    const int smem_bytes = SMEMF * 4;   // 52816

    static int cfg = 0;
    if (!cfg) {
        cudaFuncSetAttribute(vq_fused<true>,
                             cudaFuncAttributeMaxDynamicSharedMemorySize, smem_bytes);
        cudaFuncSetAttribute(vq_fused<false>,
                             cudaFuncAttributeMaxDynamicSharedMemorySize, smem_bytes);
        cfg = 1;
    }
    if (full) vq_fused<true><<<1024, 128, smem_bytes>>>(lat, emb, out);
    else      vq_fused<false><<<1024, 128, smem_bytes>>>(lat, emb, out);
}